// round 10
// baseline (speedup 1.0000x reference)
#include <cuda_runtime.h>
#include <math.h>
#include <stdint.h>

// ---------------- problem constants ----------------
#define KB   16          // batch
#define KG   2048        // group count
#define KC   384         // channels
#define KH   6           // heads
#define KDH  64          // head dim
#define KV   820         // visible tokens per row
#define KDEPTH 6
#define KBV  (KB*KV)     // 13120 rows
#define KR2  0.16f       // radius^2
#define KTILES 13        // ceil(KV/64)

// ---------------- static device scratch (no allocs allowed) ----------------
__device__ float g_bufA[KBV*KC];
__device__ float g_bufB[KBV*KC];
__device__ float g_pos [KBV*KC];
__device__ float g_hn  [KBV*KC];
__device__ float g_qkv [KBV*3*KC];
__device__ float g_obuf[KBV*KC];
__device__ float g_t4  [KBV*4*KC];
__device__ float g_ctr [KBV*3];
__device__ int   g_order[KBV];
__device__ int   g_sidx [KBV];
__device__ int   g_outrow[KBV];
__device__ unsigned long long g_nbrmask[KBV*KTILES];

// ---------------- helpers ----------------
__device__ __forceinline__ float gelu_tanh(float x) {
    const float c = 0.7978845608028654f;
    float inner = c * (x + 0.044715f * x * x * x);
    return 0.5f * x * (1.0f + tanhf(inner));
}

__device__ __forceinline__ float tf32r(float x) {
    unsigned u;
    asm("cvt.rna.tf32.f32 %0, %1;" : "=r"(u) : "f"(x));
    return __uint_as_float(u);
}

__device__ __forceinline__ void mma_tf32(float* d, const unsigned* a,
                                         const unsigned* b) {
    asm volatile(
        "mma.sync.aligned.m16n8k8.row.col.f32.tf32.tf32.f32 "
        "{%0,%1,%2,%3}, {%4,%5,%6,%7}, {%8,%9}, {%0,%1,%2,%3};\n"
        : "+f"(d[0]), "+f"(d[1]), "+f"(d[2]), "+f"(d[3])
        : "r"(a[0]), "r"(a[1]), "r"(a[2]), "r"(a[3]),
          "r"(b[0]), "r"(b[1]));
}

__device__ __forceinline__ unsigned smem_u32(const void* p) {
    unsigned r;
    asm("{ .reg .u64 t; cvta.to.shared.u64 t, %1; cvt.u32.u64 %0, t; }"
        : "=r"(r) : "l"(p));
    return r;
}

#define CP16(dst, src) \
    asm volatile("cp.async.cg.shared.global [%0], [%1], 16;\n" \
                 :: "r"(dst), "l"(src))
#define CP16Z(dst, src, sz) \
    asm volatile("cp.async.cg.shared.global [%0], [%1], 16, %2;\n" \
                 :: "r"(dst), "l"(src), "r"(sz))

__device__ __forceinline__ unsigned part1by2(unsigned x) {
    x &= 0x3ff;
    x = (x | (x << 16)) & 0x030000FFu;
    x = (x | (x << 8))  & 0x0300F00Fu;
    x = (x | (x << 4))  & 0x030C30C3u;
    x = (x | (x << 2))  & 0x09249249u;
    return x;
}

// ---------------- ragged pack ----------------
__global__ void build_order_kernel(const void* mask, int* order) {
    int b = blockIdx.x;
    if (threadIdx.x != 0) return;
    const unsigned char* m8 = (const unsigned char*)mask;
    int zc = 0;
    for (int i = 0; i < KG; i++) zc += (m8[(size_t)b*KG + i] == 0);
    int cnt = 0;
    if (zc == KV) {
        for (int i = 0; i < KG && cnt < KV; i++)
            if (m8[(size_t)b*KG + i] == 0) order[b*KV + cnt++] = i;
    } else {
        const int* m32 = (const int*)mask;
        for (int i = 0; i < KG && cnt < KV; i++)
            if (m32[(size_t)b*KG + i] == 0) order[b*KV + cnt++] = i;
    }
}

// ---------------- Morton sort of visible tokens (per batch, bitonic) --------
__global__ void sort_kernel(const float* __restrict__ centers,
                            const int* __restrict__ order,
                            int* __restrict__ sidx, int* __restrict__ outrow) {
    const int b = blockIdx.x;
    __shared__ unsigned keys[1024];
    __shared__ int      vals[1024];
    const int tid = threadIdx.x;  // 256
    for (int i = tid; i < 1024; i += 256) {
        if (i < KV) {
            int tok = order[b*KV + i];
            size_t cb = ((size_t)b*KG + tok) * 3;
            float x = centers[cb + 0], y = centers[cb + 1], z = centers[cb + 2];
            unsigned ux = min(1023, max(0, (int)(x * 1024.f)));
            unsigned uy = min(1023, max(0, (int)(y * 1024.f)));
            unsigned uz = min(1023, max(0, (int)(z * 1024.f)));
            keys[i] = (part1by2(uz) << 2) | (part1by2(uy) << 1) | part1by2(ux);
            vals[i] = i;
        } else {
            keys[i] = 0xFFFFFFFFu;
            vals[i] = i;
        }
    }
    __syncthreads();
    for (int k = 2; k <= 1024; k <<= 1) {
        for (int j = k >> 1; j > 0; j >>= 1) {
            for (int i = tid; i < 1024; i += 256) {
                int ixj = i ^ j;
                if (ixj > i) {
                    bool up = ((i & k) == 0);
                    unsigned ka = keys[i], kb2 = keys[ixj];
                    if ((ka > kb2) == up) {
                        keys[i] = kb2; keys[ixj] = ka;
                        int t = vals[i]; vals[i] = vals[ixj]; vals[ixj] = t;
                    }
                }
            }
            __syncthreads();
        }
    }
    for (int i = tid; i < KV; i += 256) {
        sidx[b*KV + i]   = vals[i];
        outrow[b*KV + i] = b*KV + vals[i];
    }
}

__global__ void gather_kernel(const float* __restrict__ tokens,
                              const float* __restrict__ centers,
                              const int* __restrict__ order,
                              const int* __restrict__ sidx,
                              float* __restrict__ x, float* __restrict__ ctr) {
    int bv = blockIdx.x;
    int b = bv / KV;
    int src = order[b*KV + sidx[bv]];
    int tid = threadIdx.x;  // 384
    x[(size_t)bv*KC + tid] = tokens[((size_t)b*KG + src)*KC + tid];
    if (tid < 3) ctr[(size_t)bv*3 + tid] = centers[((size_t)b*KG + src)*3 + tid];
}

// ---------------- neighbor bitmask precompute (sorted order) ----------------
__global__ void mask_kernel(const float* __restrict__ ctr,
                            unsigned long long* __restrict__ nbrmask) {
    const int b = blockIdx.y;
    const int q = blockIdx.x * 128 + threadIdx.x;
    __shared__ float sc[KV][3];
    for (int i = threadIdx.x; i < KV; i += 128) {
        size_t cb = ((size_t)b*KV + i) * 3;
        sc[i][0] = ctr[cb + 0];
        sc[i][1] = ctr[cb + 1];
        sc[i][2] = ctr[cb + 2];
    }
    __syncthreads();
    if (q >= KV) return;
    const float qc0 = sc[q][0], qc1 = sc[q][1], qc2 = sc[q][2];
    unsigned long long* out = nbrmask + (size_t)(b*KV + q) * KTILES;
    for (int kt = 0; kt < KTILES; kt++) {
        unsigned long long w = 0;
        const int base = kt * 64;
        const int cnt = min(64, KV - base);
        for (int j = 0; j < cnt; j++) {
            float dx = qc0 - sc[base + j][0];
            float dy = qc1 - sc[base + j][1];
            float dz = qc2 - sc[base + j][2];
            float d2 = fmaf(dx, dx, fmaf(dy, dy, dz * dz));
            if (d2 < KR2) w |= 1ull << j;
        }
        out[kt] = w;
    }
}

// ---------------- FFMA GEMM (tiny-K pos MLP layer 1) ----------------
__global__ void gemm_kernel(const float* __restrict__ A, const float* __restrict__ W,
                            const float* __restrict__ bias, float* __restrict__ C,
                            int M, int K, int N, int act, int addC) {
    __shared__ float As[16][65];
    __shared__ float Bs[16][65];
    const int tid = threadIdx.x;
    const int tx = tid & 15;
    const int ty = tid >> 4;
    const int bm = blockIdx.y * 64;
    const int bn = blockIdx.x * 64;
    float acc[4][4];
    #pragma unroll
    for (int i = 0; i < 4; i++)
        #pragma unroll
        for (int j = 0; j < 4; j++) acc[i][j] = 0.f;

    for (int k0 = 0; k0 < K; k0 += 16) {
        #pragma unroll
        for (int t = 0; t < 4; t++) {
            int idx = tid + t * 256;
            int m  = idx >> 4;
            int kk = idx & 15;
            int gm = bm + m, gk = k0 + kk;
            float v = 0.f;
            if (gk < K && gm < M) v = A[(size_t)gm * K + gk];
            As[kk][m] = v;
        }
        #pragma unroll
        for (int t = 0; t < 4; t++) {
            int idx = tid + t * 256;
            int kk = idx >> 6;
            int n  = idx & 63;
            int gk = k0 + kk, gn = bn + n;
            float v = 0.f;
            if (gk < K && gn < N) v = W[(size_t)gk * N + gn];
            Bs[kk][n] = v;
        }
        __syncthreads();
        #pragma unroll
        for (int kk = 0; kk < 16; kk++) {
            float a[4], b[4];
            #pragma unroll
            for (int i = 0; i < 4; i++) a[i] = As[kk][ty*4 + i];
            #pragma unroll
            for (int j = 0; j < 4; j++) b[j] = Bs[kk][tx*4 + j];
            #pragma unroll
            for (int i = 0; i < 4; i++)
                #pragma unroll
                for (int j = 0; j < 4; j++)
                    acc[i][j] = fmaf(a[i], b[j], acc[i][j]);
        }
        __syncthreads();
    }
    #pragma unroll
    for (int i = 0; i < 4; i++) {
        int gm = bm + ty*4 + i;
        if (gm >= M) continue;
        #pragma unroll
        for (int j = 0; j < 4; j++) {
            int gn = bn + tx*4 + j;
            if (gn >= N) continue;
            float v = acc[i][j] + bias[gn];
            if (act) v = gelu_tanh(v);
            size_t off = (size_t)gm * N + gn;
            if (addC) v += C[off];
            C[off] = v;
        }
    }
}

// ---------------- tf32 tensor-core GEMM (k-tile 32, cp.async 2-stage) -------
#define GA_S 36
#define GB_S 136
#define GST  (128*GA_S + 32*GB_S)   // 8960 floats per stage
__global__ __launch_bounds__(256, 2)
void gemm_tf32_kernel(const float* __restrict__ A, const float* __restrict__ W,
                      const float* __restrict__ bias, float* __restrict__ C,
                      int M, int K, int N, int act, int addC) {
    extern __shared__ float gsm[];

    const int tid  = threadIdx.x;
    const int lane = tid & 31;
    const int w    = tid >> 5;
    const int wm   = (w & 3) * 32;
    const int wn   = (w >> 2) * 64;
    const int bm   = blockIdx.y * 128;
    const int bn   = blockIdx.x * 128;
    const int g    = lane >> 2, c = lane & 3;

    float acc[2][8][4];
    #pragma unroll
    for (int mt = 0; mt < 2; mt++)
        #pragma unroll
        for (int nt = 0; nt < 8; nt++)
            #pragma unroll
            for (int r = 0; r < 4; r++) acc[mt][nt][r] = 0.f;

    const int ktiles = K >> 5;

    #define GSTAGE_TILE(ktArg)                                            \
    do {                                                                  \
        float* sA_ = gsm + ((ktArg) & 1) * GST;                           \
        float* sB_ = sA_ + 128 * GA_S;                                    \
        const int k0_ = (ktArg) << 5;                                     \
        _Pragma("unroll")                                                 \
        for (int t = 0; t < 4; t++) {                                     \
            int i = tid + t * 256;                                        \
            int row = i >> 3, kq = (i & 7) * 4;                           \
            int gm = bm + row; if (gm > M - 1) gm = M - 1;                \
            CP16(smem_u32(&sA_[row * GA_S + kq]),                         \
                 A + (size_t)gm * K + k0_ + kq);                          \
        }                                                                 \
        _Pragma("unroll")                                                 \
        for (int t = 0; t < 4; t++) {                                     \
            int i = tid + t * 256;                                        \
            int kr = i >> 5, nq = (i & 31) * 4;                           \
            CP16(smem_u32(&sB_[kr * GB_S + nq]),                          \
                 W + (size_t)(k0_ + kr) * N + bn + nq);                   \
        }                                                                 \
        asm volatile("cp.async.commit_group;\n");                         \
    } while (0)

    GSTAGE_TILE(0);

    for (int kt = 0; kt < ktiles; kt++) {
        if (kt + 1 < ktiles) {
            GSTAGE_TILE(kt + 1);
            asm volatile("cp.async.wait_group 1;\n");
        } else {
            asm volatile("cp.async.wait_group 0;\n");
        }
        __syncthreads();

        const float* sA = gsm + (kt & 1) * GST;
        const float* sB = sA + 128 * GA_S;
        #pragma unroll
        for (int k8 = 0; k8 < 4; k8++) {
            const int kb = k8 * 8;
            unsigned af[2][4], bf[8][2];
            const int arow = wm + g;
            #pragma unroll
            for (int mt = 0; mt < 2; mt++) {
                const float* pa = &sA[(arow + mt * 16) * GA_S + kb + c];
                af[mt][0] = __float_as_uint(pa[0]);
                af[mt][1] = __float_as_uint(pa[8 * GA_S]);
                af[mt][2] = __float_as_uint(pa[4]);
                af[mt][3] = __float_as_uint(pa[8 * GA_S + 4]);
            }
            #pragma unroll
            for (int nt = 0; nt < 8; nt++) {
                const float* pb = &sB[(kb + c) * GB_S + wn + nt * 8 + g];
                bf[nt][0] = __float_as_uint(pb[0]);
                bf[nt][1] = __float_as_uint(pb[4 * GB_S]);
            }
            #pragma unroll
            for (int mt = 0; mt < 2; mt++)
                #pragma unroll
                for (int nt = 0; nt < 8; nt++)
                    mma_tf32(acc[mt][nt], af[mt], bf[nt]);
        }
        __syncthreads();
    }

    #pragma unroll
    for (int mt = 0; mt < 2; mt++) {
        int rbase = bm + wm + mt * 16 + g;
        #pragma unroll
        for (int half = 0; half < 2; half++) {
            int r = rbase + half * 8;
            if (r >= M) continue;
            #pragma unroll
            for (int nt = 0; nt < 8; nt++) {
                int cix = bn + wn + nt * 8 + 2 * c;
                float v0 = acc[mt][nt][half * 2 + 0] + bias[cix];
                float v1 = acc[mt][nt][half * 2 + 1] + bias[cix + 1];
                if (act) { v0 = gelu_tanh(v0); v1 = gelu_tanh(v1); }
                size_t off = (size_t)r * N + cix;
                if (addC) { v0 += C[off]; v1 += C[off + 1]; }
                float2 vv = make_float2(v0, v1);
                *reinterpret_cast<float2*>(&C[off]) = vv;
            }
        }
    }
}

// ---------------- LayerNorm (warp per row; optional output remap) -----------
__global__ __launch_bounds__(256)
void ln_kernel(const float* __restrict__ x, const float* __restrict__ pos,
               float* __restrict__ hout, float* __restrict__ hn,
               const float* __restrict__ w, const float* __restrict__ bb,
               const int* __restrict__ outmap) {
    const int row  = blockIdx.x * 8 + (threadIdx.x >> 5);
    const int lane = threadIdx.x & 31;
    size_t base = (size_t)row * KC;
    float v[12];
    float s = 0.f;
    #pragma unroll
    for (int i = 0; i < 12; i++) {
        int c = lane + i * 32;
        float t = x[base + c];
        if (pos) t += pos[base + c];
        v[i] = t;
        s += t;
        if (hout) hout[base + c] = t;
    }
    #pragma unroll
    for (int o = 16; o; o >>= 1) s += __shfl_xor_sync(0xffffffffu, s, o);
    float mean = s * (1.0f / KC);
    float s2 = 0.f;
    #pragma unroll
    for (int i = 0; i < 12; i++) {
        float d = v[i] - mean;
        s2 += d * d;
    }
    #pragma unroll
    for (int o = 16; o; o >>= 1) s2 += __shfl_xor_sync(0xffffffffu, s2, o);
    float inv = rsqrtf(s2 * (1.0f / KC) + 1e-5f);
    size_t obase = outmap ? (size_t)outmap[row] * KC : base;
    #pragma unroll
    for (int i = 0; i < 12; i++) {
        int c = lane + i * 32;
        hn[obase + c] = (v[i] - mean) * inv * w[c] + bb[c];
    }
}

// ---------------- tensor-core masked flash attention ------------------------
// 256 threads = 8 warps = 128 queries/CTA. Dynamic smem:
//   [ks 64x68][vs 64x72][pextra 4x16x68]  = 53,248 B
// P: warps 0-3 alias onto ks (free after S-MMAs), warps 4-7 use pextra.
// Warp-uniform 8-key-group liveness + per-lane PREDICATED exp.
#define AT_KS 68
#define AT_VS 72
#define AT_PS 68
#define AT_VS_OFF (64*AT_KS)             // 4352
#define AT_PX_OFF (AT_VS_OFF + 64*AT_VS) // 8960
#define AT_SMEM_FLOATS (AT_PX_OFF + 4*16*AT_PS)  // 13312 -> 53,248 B
__global__ __launch_bounds__(256)
void attn_mma_kernel(const float* __restrict__ qkv,
                     const unsigned long long* __restrict__ nbrmask,
                     float* __restrict__ o) {
    extern __shared__ float asmem[];
    float* ks = asmem;
    float* vs = asmem + AT_VS_OFF;
    const int qt = blockIdx.x, h = blockIdx.y, b = blockIdx.z;
    const int tid  = threadIdx.x;
    const int lane = tid & 31;
    const int w    = tid >> 5;
    const int g    = lane >> 2;
    const int c    = lane & 3;
    float* spw = (w < 4) ? &ks[w * 16 * AT_PS]
                         : &asmem[AT_PX_OFF + (w - 4) * 16 * AT_PS];

    const int qr_a = qt * 128 + w * 16 + g;
    const int qr_b = qr_a + 8;
    const int qa = min(qr_a, KV - 1);
    const int qb = min(qr_b, KV - 1);

    float qf[8][4];
    {
        const float* Qa = qkv + ((size_t)b * KV + qa) * (3*KC) + h * KDH;
        const float* Qb = qkv + ((size_t)b * KV + qb) * (3*KC) + h * KDH;
        #pragma unroll
        for (int k8 = 0; k8 < 8; k8++) {
            qf[k8][0] = tf32r(Qa[k8*8 + c])     * 0.125f;
            qf[k8][1] = tf32r(Qb[k8*8 + c])     * 0.125f;
            qf[k8][2] = tf32r(Qa[k8*8 + c + 4]) * 0.125f;
            qf[k8][3] = tf32r(Qb[k8*8 + c + 4]) * 0.125f;
        }
    }
    const unsigned long long* mra = nbrmask + ((size_t)b*KV + qa) * KTILES;
    const unsigned long long* mrb = nbrmask + ((size_t)b*KV + qb) * KTILES;

    float m0 = -1e30f, m1 = -1e30f, l0 = 0.f, l1 = 0.f;
    float oacc[8][4];
    #pragma unroll
    for (int nt = 0; nt < 8; nt++)
        #pragma unroll
        for (int r = 0; r < 4; r++) oacc[nt][r] = 0.f;

    for (int kt = 0; kt < KTILES; kt++) {
        const int cnt = min(64, KV - kt * 64);
        // stage K/V tile via cp.async (256 threads, 4 iters, zero-fill)
        #pragma unroll
        for (int it = 0; it < 4; it++) {
            int idx = tid + it * 256;
            int j = idx >> 4, d4 = idx & 15;
            int jc = min(j, cnt - 1);
            const float* src = qkv + ((size_t)b * KV + kt*64 + jc) * (3*KC)
                             + h * KDH + d4 * 4;
            unsigned sz = (j < cnt) ? 16u : 0u;
            CP16Z(smem_u32(&ks[j * AT_KS + d4 * 4]), src + KC,   sz);
            CP16Z(smem_u32(&vs[j * AT_VS + d4 * 4]), src + 2*KC, sz);
        }
        asm volatile("cp.async.commit_group;\n");
        asm volatile("cp.async.wait_group 0;\n");
        __syncthreads();

        const unsigned long long mwa = mra[kt];
        const unsigned long long mwb = mrb[kt];
        // warp-union mask -> 8-bit key-group liveness (warp-uniform)
        unsigned long long mwu = mwa | mwb;
        #pragma unroll
        for (int off = 1; off < 32; off <<= 1)
            mwu |= __shfl_xor_sync(0xffffffffu, mwu, off);
        unsigned lv = 0;
        #pragma unroll
        for (int kg = 0; kg < 8; kg++)
            if ((mwu >> (kg * 8)) & 0xFFull) lv |= 1u << kg;

        float sacc[8][4];
        if (lv) {
            #pragma unroll
            for (int nt = 0; nt < 8; nt++)
                #pragma unroll
                for (int r = 0; r < 4; r++) sacc[nt][r] = 0.f;
            #pragma unroll
            for (int k8 = 0; k8 < 8; k8++) {
                #pragma unroll
                for (int nt = 0; nt < 8; nt++) {
                    if (!((lv >> nt) & 1)) continue;
                    unsigned bf[2];
                    const float* pb = &ks[(nt*8 + g) * AT_KS + k8*8 + c];
                    bf[0] = __float_as_uint(pb[0]);
                    bf[1] = __float_as_uint(pb[4]);
                    mma_tf32(sacc[nt], reinterpret_cast<const unsigned*>(qf[k8]), bf);
                }
            }
        }
        __syncthreads();   // ks reads done -> warps 0-3 may write P there

        if (lv) {
            float tm0 = -1e30f, tm1 = -1e30f;
            #pragma unroll
            for (int nt = 0; nt < 8; nt++) {
                if (!((lv >> nt) & 1)) continue;
                int col = nt*8 + 2*c;
                sacc[nt][0] = ((mwa >> col)     & 1) ? sacc[nt][0] : -1e30f;
                sacc[nt][1] = ((mwa >> (col+1)) & 1) ? sacc[nt][1] : -1e30f;
                sacc[nt][2] = ((mwb >> col)     & 1) ? sacc[nt][2] : -1e30f;
                sacc[nt][3] = ((mwb >> (col+1)) & 1) ? sacc[nt][3] : -1e30f;
                tm0 = fmaxf(tm0, fmaxf(sacc[nt][0], sacc[nt][1]));
                tm1 = fmaxf(tm1, fmaxf(sacc[nt][2], sacc[nt][3]));
            }
            tm0 = fmaxf(tm0, __shfl_xor_sync(0xffffffffu, tm0, 1));
            tm0 = fmaxf(tm0, __shfl_xor_sync(0xffffffffu, tm0, 2));
            tm1 = fmaxf(tm1, __shfl_xor_sync(0xffffffffu, tm1, 1));
            tm1 = fmaxf(tm1, __shfl_xor_sync(0xffffffffu, tm1, 2));
            const float mn0 = fmaxf(m0, tm0);
            const float mn1 = fmaxf(m1, tm1);
            const float cr0 = __expf(m0 - mn0);
            const float cr1 = __expf(m1 - mn1);
            m0 = mn0; m1 = mn1;

            float ps0 = 0.f, ps1 = 0.f;
            #pragma unroll
            for (int nt = 0; nt < 8; nt++) {
                if (!((lv >> nt) & 1)) continue;
                int col = nt*8 + 2*c;
                // per-lane PREDICATED exp: masked lanes never issue MUFU work
                float p00 = 0.f, p01 = 0.f, p10 = 0.f, p11 = 0.f;
                if (sacc[nt][0] > -1e29f) p00 = __expf(sacc[nt][0] - mn0);
                if (sacc[nt][1] > -1e29f) p01 = __expf(sacc[nt][1] - mn0);
                if (sacc[nt][2] > -1e29f) p10 = __expf(sacc[nt][2] - mn1);
                if (sacc[nt][3] > -1e29f) p11 = __expf(sacc[nt][3] - mn1);
                ps0 += p00 + p01;
                ps1 += p10 + p11;
                *reinterpret_cast<float2*>(&spw[g * AT_PS + col]) =
                    make_float2(tf32r(p00), tf32r(p01));
                *reinterpret_cast<float2*>(&spw[(g + 8) * AT_PS + col]) =
                    make_float2(tf32r(p10), tf32r(p11));
            }
            ps0 += __shfl_xor_sync(0xffffffffu, ps0, 1);
            ps0 += __shfl_xor_sync(0xffffffffu, ps0, 2);
            ps1 += __shfl_xor_sync(0xffffffffu, ps1, 1);
            ps1 += __shfl_xor_sync(0xffffffffu, ps1, 2);
            l0 = l0 * cr0 + ps0;
            l1 = l1 * cr1 + ps1;
            #pragma unroll
            for (int nt = 0; nt < 8; nt++) {
                oacc[nt][0] *= cr0; oacc[nt][1] *= cr0;
                oacc[nt][2] *= cr1; oacc[nt][3] *= cr1;
            }
            __syncwarp();

            // O += P @ V (skip dead key-groups k8)
            #pragma unroll
            for (int k8 = 0; k8 < 8; k8++) {
                if (!((lv >> k8) & 1)) continue;
                unsigned af[4];
                af[0] = __float_as_uint(spw[g * AT_PS + k8*8 + c]);
                af[1] = __float_as_uint(spw[(g + 8) * AT_PS + k8*8 + c]);
                af[2] = __float_as_uint(spw[g * AT_PS + k8*8 + c + 4]);
                af[3] = __float_as_uint(spw[(g + 8) * AT_PS + k8*8 + c + 4]);
                #pragma unroll
                for (int nt = 0; nt < 8; nt++) {
                    unsigned bf[2];
                    bf[0] = __float_as_uint(vs[(k8*8 + c)     * AT_VS + nt*8 + g]);
                    bf[1] = __float_as_uint(vs[(k8*8 + c + 4) * AT_VS + nt*8 + g]);
                    mma_tf32(oacc[nt], af, bf);
                }
            }
        }
        __syncthreads();   // protect ks/vs (and aliased P) for next staging
    }

    const float il0 = 1.0f / l0;   // self always unmasked -> l > 0
    const float il1 = 1.0f / l1;
    if (qr_a < KV) {
        size_t ob = ((size_t)b * KV + qr_a) * KC + h * KDH;
        #pragma unroll
        for (int nt = 0; nt < 8; nt++)
            *reinterpret_cast<float2*>(&o[ob + nt*8 + 2*c]) =
                make_float2(oacc[nt][0] * il0, oacc[nt][1] * il0);
    }
    if (qr_b < KV) {
        size_t ob = ((size_t)b * KV + qr_b) * KC + h * KDH;
        #pragma unroll
        for (int nt = 0; nt < 8; nt++)
            *reinterpret_cast<float2*>(&o[ob + nt*8 + 2*c]) =
                make_float2(oacc[nt][2] * il1, oacc[nt][3] * il1);
    }
}

// ---------------- launcher ----------------
extern "C" void kernel_launch(void* const* d_in, const int* in_sizes, int n_in,
                              void* d_out, int out_size) {
    const float* tokens  = (const float*)d_in[0];
    const float* centers = (const float*)d_in[1];
    const void*  mask    = d_in[2];
    const float* pos_w1  = (const float*)d_in[3];
    const float* pos_b1  = (const float*)d_in[4];
    const float* pos_w2  = (const float*)d_in[5];
    const float* pos_b2  = (const float*)d_in[6];
    const float* ln1_w   = (const float*)d_in[7];
    const float* ln1_b   = (const float*)d_in[8];
    const float* qkv_w   = (const float*)d_in[9];
    const float* qkv_b   = (const float*)d_in[10];
    const float* proj_w  = (const float*)d_in[11];
    const float* proj_b  = (const float*)d_in[12];
    const float* ln2_w   = (const float*)d_in[13];
    const float* ln2_b   = (const float*)d_in[14];
    const float* fc1_w   = (const float*)d_in[15];
    const float* fc1_b   = (const float*)d_in[16];
    const float* fc2_w   = (const float*)d_in[17];
    const float* fc2_b   = (const float*)d_in[18];
    const float* lnf_w   = (const float*)d_in[19];
    const float* lnf_b   = (const float*)d_in[20];

    float *bufA, *bufB, *pos, *hn, *qkv, *obuf, *t4, *ctr;
    int *order, *sidx, *outrow;
    unsigned long long* nbrmask;
    cudaGetSymbolAddress((void**)&bufA,   g_bufA);
    cudaGetSymbolAddress((void**)&bufB,   g_bufB);
    cudaGetSymbolAddress((void**)&pos,    g_pos);
    cudaGetSymbolAddress((void**)&hn,     g_hn);
    cudaGetSymbolAddress((void**)&qkv,    g_qkv);
    cudaGetSymbolAddress((void**)&obuf,   g_obuf);
    cudaGetSymbolAddress((void**)&t4,     g_t4);
    cudaGetSymbolAddress((void**)&ctr,    g_ctr);
    cudaGetSymbolAddress((void**)&order,  g_order);
    cudaGetSymbolAddress((void**)&sidx,   g_sidx);
    cudaGetSymbolAddress((void**)&outrow, g_outrow);
    cudaGetSymbolAddress((void**)&nbrmask, g_nbrmask);

    const int GEMM_SMEM = 2 * GST * sizeof(float);        // 71,680 B
    const int ATT_SMEM  = AT_SMEM_FLOATS * sizeof(float); // 53,248 B
    cudaFuncSetAttribute(gemm_tf32_kernel,
                         cudaFuncAttributeMaxDynamicSharedMemorySize, GEMM_SMEM);
    cudaFuncSetAttribute(attn_mma_kernel,
                         cudaFuncAttributeMaxDynamicSharedMemorySize, ATT_SMEM);

    const int M = KBV;                 // 13120
    const dim3 blk(256);
    const int gyT = (M + 127) / 128;
    const int gyF = (M + 63) / 64;
    const int lnG = M / 8;             // 1640
    const int aqt = (KV + 127) / 128;  // 7

    // ragged pack + spatial sort
    build_order_kernel<<<KB, 32>>>(mask, order);
    sort_kernel<<<KB, 256>>>(centers, order, sidx, outrow);
    gather_kernel<<<KBV, KC>>>(tokens, centers, order, sidx, bufA, ctr);

    // neighbor bitmask (sorted order; reused by all 36 attention passes)
    mask_kernel<<<dim3((KV + 127) / 128, KB), 128>>>(ctr, nbrmask);

    // positional MLP
    gemm_kernel<<<dim3(KC/64, gyF), blk>>>(ctr, pos_w1, pos_b1, hn, M, 3, KC, 1, 0);
    gemm_tf32_kernel<<<dim3(KC/128, gyT), blk, GEMM_SMEM>>>(hn, pos_w2, pos_b2, pos,
                                                            M, KC, KC, 0, 0);

    float* cur = bufA;
    float* oth = bufB;
    for (int l = 0; l < KDEPTH; l++) {
        ln_kernel<<<lnG, 256>>>(cur, pos, oth, hn, ln1_w + l*KC, ln1_b + l*KC, nullptr);
        gemm_tf32_kernel<<<dim3(3*KC/128, gyT), blk, GEMM_SMEM>>>(
            hn, qkv_w + (size_t)l*KC*3*KC, qkv_b + (size_t)l*3*KC, qkv,
            M, KC, 3*KC, 0, 0);
        attn_mma_kernel<<<dim3(aqt, KH, KB), 256, ATT_SMEM>>>(qkv, nbrmask, obuf);
        gemm_tf32_kernel<<<dim3(KC/128, gyT), blk, GEMM_SMEM>>>(
            obuf, proj_w + (size_t)l*KC*KC, proj_b + (size_t)l*KC, oth,
            M, KC, KC, 0, 1);
        ln_kernel<<<lnG, 256>>>(oth, nullptr, nullptr, hn, ln2_w + l*KC, ln2_b + l*KC, nullptr);
        gemm_tf32_kernel<<<dim3(4*KC/128, gyT), blk, GEMM_SMEM>>>(
            hn, fc1_w + (size_t)l*KC*4*KC, fc1_b + (size_t)l*4*KC, t4,
            M, KC, 4*KC, 1, 0);
        gemm_tf32_kernel<<<dim3(KC/128, gyT), blk, GEMM_SMEM>>>(
            t4, fc2_w + (size_t)l*4*KC*KC, fc2_b + (size_t)l*KC, oth,
            M, 4*KC, KC, 0, 1);
        float* tmp = cur; cur = oth; oth = tmp;
    }
    // final LN, scattered back to original visible order
    ln_kernel<<<lnG, 256>>>(cur, nullptr, nullptr, (float*)d_out, lnf_w, lnf_b, outrow);
}

// round 11
// speedup vs baseline: 1.0343x; 1.0343x over previous
#include <cuda_runtime.h>
#include <math.h>
#include <stdint.h>

// ---------------- problem constants ----------------
#define KB   16          // batch
#define KG   2048        // group count
#define KC   384         // channels
#define KH   6           // heads
#define KDH  64          // head dim
#define KV   820         // visible tokens per row
#define KDEPTH 6
#define KBV  (KB*KV)     // 13120 rows
#define KR2  0.16f       // radius^2
#define KTILES 13        // ceil(KV/64)

// ---------------- static device scratch (no allocs allowed) ----------------
__device__ float g_bufA[KBV*KC];
__device__ float g_bufB[KBV*KC];
__device__ float g_pos [KBV*KC];
__device__ float g_hn  [KBV*KC];
__device__ float g_qkv [KBV*3*KC];
__device__ float g_obuf[KBV*KC];
__device__ float g_t4  [KBV*4*KC];
__device__ float g_ctr [KBV*3];
__device__ int   g_order[KBV];
__device__ int   g_sidx [KBV];
__device__ int   g_outrow[KBV];
__device__ unsigned long long g_nbrmask[KBV*KTILES];

// ---------------- helpers ----------------
__device__ __forceinline__ float gelu_tanh(float x) {
    const float c = 0.7978845608028654f;
    float inner = c * (x + 0.044715f * x * x * x);
    return 0.5f * x * (1.0f + tanhf(inner));
}

__device__ __forceinline__ float tf32r(float x) {
    unsigned u;
    asm("cvt.rna.tf32.f32 %0, %1;" : "=r"(u) : "f"(x));
    return __uint_as_float(u);
}

__device__ __forceinline__ void mma_tf32(float* d, const unsigned* a,
                                         const unsigned* b) {
    asm volatile(
        "mma.sync.aligned.m16n8k8.row.col.f32.tf32.tf32.f32 "
        "{%0,%1,%2,%3}, {%4,%5,%6,%7}, {%8,%9}, {%0,%1,%2,%3};\n"
        : "+f"(d[0]), "+f"(d[1]), "+f"(d[2]), "+f"(d[3])
        : "r"(a[0]), "r"(a[1]), "r"(a[2]), "r"(a[3]),
          "r"(b[0]), "r"(b[1]));
}

__device__ __forceinline__ unsigned smem_u32(const void* p) {
    unsigned r;
    asm("{ .reg .u64 t; cvta.to.shared.u64 t, %1; cvt.u32.u64 %0, t; }"
        : "=r"(r) : "l"(p));
    return r;
}

#define CP16(dst, src) \
    asm volatile("cp.async.cg.shared.global [%0], [%1], 16;\n" \
                 :: "r"(dst), "l"(src))
#define CP16Z(dst, src, sz) \
    asm volatile("cp.async.cg.shared.global [%0], [%1], 16, %2;\n" \
                 :: "r"(dst), "l"(src), "r"(sz))

__device__ __forceinline__ unsigned part1by2(unsigned x) {
    x &= 0x3ff;
    x = (x | (x << 16)) & 0x030000FFu;
    x = (x | (x << 8))  & 0x0300F00Fu;
    x = (x | (x << 4))  & 0x030C30C3u;
    x = (x | (x << 2))  & 0x09249249u;
    return x;
}

// ---------------- ragged pack ----------------
__global__ void build_order_kernel(const void* mask, int* order) {
    int b = blockIdx.x;
    if (threadIdx.x != 0) return;
    const unsigned char* m8 = (const unsigned char*)mask;
    int zc = 0;
    for (int i = 0; i < KG; i++) zc += (m8[(size_t)b*KG + i] == 0);
    int cnt = 0;
    if (zc == KV) {
        for (int i = 0; i < KG && cnt < KV; i++)
            if (m8[(size_t)b*KG + i] == 0) order[b*KV + cnt++] = i;
    } else {
        const int* m32 = (const int*)mask;
        for (int i = 0; i < KG && cnt < KV; i++)
            if (m32[(size_t)b*KG + i] == 0) order[b*KV + cnt++] = i;
    }
}

// ---------------- Morton sort of visible tokens (per batch, bitonic) --------
__global__ void sort_kernel(const float* __restrict__ centers,
                            const int* __restrict__ order,
                            int* __restrict__ sidx, int* __restrict__ outrow) {
    const int b = blockIdx.x;
    __shared__ unsigned keys[1024];
    __shared__ int      vals[1024];
    const int tid = threadIdx.x;  // 256
    for (int i = tid; i < 1024; i += 256) {
        if (i < KV) {
            int tok = order[b*KV + i];
            size_t cb = ((size_t)b*KG + tok) * 3;
            float x = centers[cb + 0], y = centers[cb + 1], z = centers[cb + 2];
            unsigned ux = min(1023, max(0, (int)(x * 1024.f)));
            unsigned uy = min(1023, max(0, (int)(y * 1024.f)));
            unsigned uz = min(1023, max(0, (int)(z * 1024.f)));
            keys[i] = (part1by2(uz) << 2) | (part1by2(uy) << 1) | part1by2(ux);
            vals[i] = i;
        } else {
            keys[i] = 0xFFFFFFFFu;
            vals[i] = i;
        }
    }
    __syncthreads();
    for (int k = 2; k <= 1024; k <<= 1) {
        for (int j = k >> 1; j > 0; j >>= 1) {
            for (int i = tid; i < 1024; i += 256) {
                int ixj = i ^ j;
                if (ixj > i) {
                    bool up = ((i & k) == 0);
                    unsigned ka = keys[i], kb2 = keys[ixj];
                    if ((ka > kb2) == up) {
                        keys[i] = kb2; keys[ixj] = ka;
                        int t = vals[i]; vals[i] = vals[ixj]; vals[ixj] = t;
                    }
                }
            }
            __syncthreads();
        }
    }
    for (int i = tid; i < KV; i += 256) {
        sidx[b*KV + i]   = vals[i];
        outrow[b*KV + i] = b*KV + vals[i];
    }
}

__global__ void gather_kernel(const float* __restrict__ tokens,
                              const float* __restrict__ centers,
                              const int* __restrict__ order,
                              const int* __restrict__ sidx,
                              float* __restrict__ x, float* __restrict__ ctr) {
    int bv = blockIdx.x;
    int b = bv / KV;
    int src = order[b*KV + sidx[bv]];
    int tid = threadIdx.x;  // 384
    x[(size_t)bv*KC + tid] = tokens[((size_t)b*KG + src)*KC + tid];
    if (tid < 3) ctr[(size_t)bv*3 + tid] = centers[((size_t)b*KG + src)*3 + tid];
}

// ---------------- neighbor bitmask precompute (sorted order) ----------------
__global__ void mask_kernel(const float* __restrict__ ctr,
                            unsigned long long* __restrict__ nbrmask) {
    const int b = blockIdx.y;
    const int q = blockIdx.x * 128 + threadIdx.x;
    __shared__ float sc[KV][3];
    for (int i = threadIdx.x; i < KV; i += 128) {
        size_t cb = ((size_t)b*KV + i) * 3;
        sc[i][0] = ctr[cb + 0];
        sc[i][1] = ctr[cb + 1];
        sc[i][2] = ctr[cb + 2];
    }
    __syncthreads();
    if (q >= KV) return;
    const float qc0 = sc[q][0], qc1 = sc[q][1], qc2 = sc[q][2];
    unsigned long long* out = nbrmask + (size_t)(b*KV + q) * KTILES;
    for (int kt = 0; kt < KTILES; kt++) {
        unsigned long long w = 0;
        const int base = kt * 64;
        const int cnt = min(64, KV - base);
        for (int j = 0; j < cnt; j++) {
            float dx = qc0 - sc[base + j][0];
            float dy = qc1 - sc[base + j][1];
            float dz = qc2 - sc[base + j][2];
            float d2 = fmaf(dx, dx, fmaf(dy, dy, dz * dz));
            if (d2 < KR2) w |= 1ull << j;
        }
        out[kt] = w;
    }
}

// ---------------- FFMA GEMM (tiny-K pos MLP layer 1) ----------------
__global__ void gemm_kernel(const float* __restrict__ A, const float* __restrict__ W,
                            const float* __restrict__ bias, float* __restrict__ C,
                            int M, int K, int N, int act, int addC) {
    __shared__ float As[16][65];
    __shared__ float Bs[16][65];
    const int tid = threadIdx.x;
    const int tx = tid & 15;
    const int ty = tid >> 4;
    const int bm = blockIdx.y * 64;
    const int bn = blockIdx.x * 64;
    float acc[4][4];
    #pragma unroll
    for (int i = 0; i < 4; i++)
        #pragma unroll
        for (int j = 0; j < 4; j++) acc[i][j] = 0.f;

    for (int k0 = 0; k0 < K; k0 += 16) {
        #pragma unroll
        for (int t = 0; t < 4; t++) {
            int idx = tid + t * 256;
            int m  = idx >> 4;
            int kk = idx & 15;
            int gm = bm + m, gk = k0 + kk;
            float v = 0.f;
            if (gk < K && gm < M) v = A[(size_t)gm * K + gk];
            As[kk][m] = v;
        }
        #pragma unroll
        for (int t = 0; t < 4; t++) {
            int idx = tid + t * 256;
            int kk = idx >> 6;
            int n  = idx & 63;
            int gk = k0 + kk, gn = bn + n;
            float v = 0.f;
            if (gk < K && gn < N) v = W[(size_t)gk * N + gn];
            Bs[kk][n] = v;
        }
        __syncthreads();
        #pragma unroll
        for (int kk = 0; kk < 16; kk++) {
            float a[4], b[4];
            #pragma unroll
            for (int i = 0; i < 4; i++) a[i] = As[kk][ty*4 + i];
            #pragma unroll
            for (int j = 0; j < 4; j++) b[j] = Bs[kk][tx*4 + j];
            #pragma unroll
            for (int i = 0; i < 4; i++)
                #pragma unroll
                for (int j = 0; j < 4; j++)
                    acc[i][j] = fmaf(a[i], b[j], acc[i][j]);
        }
        __syncthreads();
    }
    #pragma unroll
    for (int i = 0; i < 4; i++) {
        int gm = bm + ty*4 + i;
        if (gm >= M) continue;
        #pragma unroll
        for (int j = 0; j < 4; j++) {
            int gn = bn + tx*4 + j;
            if (gn >= N) continue;
            float v = acc[i][j] + bias[gn];
            if (act) v = gelu_tanh(v);
            size_t off = (size_t)gm * N + gn;
            if (addC) v += C[off];
            C[off] = v;
        }
    }
}

// ---------------- tf32 tensor-core GEMM (k-tile 32, cp.async 2-stage) -------
#define GA_S 36
#define GB_S 136
#define GST  (128*GA_S + 32*GB_S)   // 8960 floats per stage
__global__ __launch_bounds__(256, 2)
void gemm_tf32_kernel(const float* __restrict__ A, const float* __restrict__ W,
                      const float* __restrict__ bias, float* __restrict__ C,
                      int M, int K, int N, int act, int addC) {
    extern __shared__ float gsm[];

    const int tid  = threadIdx.x;
    const int lane = tid & 31;
    const int w    = tid >> 5;
    const int wm   = (w & 3) * 32;
    const int wn   = (w >> 2) * 64;
    const int bm   = blockIdx.y * 128;
    const int bn   = blockIdx.x * 128;
    const int g    = lane >> 2, c = lane & 3;

    float acc[2][8][4];
    #pragma unroll
    for (int mt = 0; mt < 2; mt++)
        #pragma unroll
        for (int nt = 0; nt < 8; nt++)
            #pragma unroll
            for (int r = 0; r < 4; r++) acc[mt][nt][r] = 0.f;

    const int ktiles = K >> 5;

    #define GSTAGE_TILE(ktArg)                                            \
    do {                                                                  \
        float* sA_ = gsm + ((ktArg) & 1) * GST;                           \
        float* sB_ = sA_ + 128 * GA_S;                                    \
        const int k0_ = (ktArg) << 5;                                     \
        _Pragma("unroll")                                                 \
        for (int t = 0; t < 4; t++) {                                     \
            int i = tid + t * 256;                                        \
            int row = i >> 3, kq = (i & 7) * 4;                           \
            int gm = bm + row; if (gm > M - 1) gm = M - 1;                \
            CP16(smem_u32(&sA_[row * GA_S + kq]),                         \
                 A + (size_t)gm * K + k0_ + kq);                          \
        }                                                                 \
        _Pragma("unroll")                                                 \
        for (int t = 0; t < 4; t++) {                                     \
            int i = tid + t * 256;                                        \
            int kr = i >> 5, nq = (i & 31) * 4;                           \
            CP16(smem_u32(&sB_[kr * GB_S + nq]),                          \
                 W + (size_t)(k0_ + kr) * N + bn + nq);                   \
        }                                                                 \
        asm volatile("cp.async.commit_group;\n");                         \
    } while (0)

    GSTAGE_TILE(0);

    for (int kt = 0; kt < ktiles; kt++) {
        if (kt + 1 < ktiles) {
            GSTAGE_TILE(kt + 1);
            asm volatile("cp.async.wait_group 1;\n");
        } else {
            asm volatile("cp.async.wait_group 0;\n");
        }
        __syncthreads();

        const float* sA = gsm + (kt & 1) * GST;
        const float* sB = sA + 128 * GA_S;
        #pragma unroll
        for (int k8 = 0; k8 < 4; k8++) {
            const int kb = k8 * 8;
            unsigned af[2][4], bf[8][2];
            const int arow = wm + g;
            #pragma unroll
            for (int mt = 0; mt < 2; mt++) {
                const float* pa = &sA[(arow + mt * 16) * GA_S + kb + c];
                af[mt][0] = __float_as_uint(pa[0]);
                af[mt][1] = __float_as_uint(pa[8 * GA_S]);
                af[mt][2] = __float_as_uint(pa[4]);
                af[mt][3] = __float_as_uint(pa[8 * GA_S + 4]);
            }
            #pragma unroll
            for (int nt = 0; nt < 8; nt++) {
                const float* pb = &sB[(kb + c) * GB_S + wn + nt * 8 + g];
                bf[nt][0] = __float_as_uint(pb[0]);
                bf[nt][1] = __float_as_uint(pb[4 * GB_S]);
            }
            #pragma unroll
            for (int mt = 0; mt < 2; mt++)
                #pragma unroll
                for (int nt = 0; nt < 8; nt++)
                    mma_tf32(acc[mt][nt], af[mt], bf[nt]);
        }
        __syncthreads();
    }

    #pragma unroll
    for (int mt = 0; mt < 2; mt++) {
        int rbase = bm + wm + mt * 16 + g;
        #pragma unroll
        for (int half = 0; half < 2; half++) {
            int r = rbase + half * 8;
            if (r >= M) continue;
            #pragma unroll
            for (int nt = 0; nt < 8; nt++) {
                int cix = bn + wn + nt * 8 + 2 * c;
                float v0 = acc[mt][nt][half * 2 + 0] + bias[cix];
                float v1 = acc[mt][nt][half * 2 + 1] + bias[cix + 1];
                if (act) { v0 = gelu_tanh(v0); v1 = gelu_tanh(v1); }
                size_t off = (size_t)r * N + cix;
                if (addC) { v0 += C[off]; v1 += C[off + 1]; }
                float2 vv = make_float2(v0, v1);
                *reinterpret_cast<float2*>(&C[off]) = vv;
            }
        }
    }
}

// ---------------- LayerNorm (warp per row; optional output remap) -----------
__global__ __launch_bounds__(256)
void ln_kernel(const float* __restrict__ x, const float* __restrict__ pos,
               float* __restrict__ hout, float* __restrict__ hn,
               const float* __restrict__ w, const float* __restrict__ bb,
               const int* __restrict__ outmap) {
    const int row  = blockIdx.x * 8 + (threadIdx.x >> 5);
    const int lane = threadIdx.x & 31;
    size_t base = (size_t)row * KC;
    float v[12];
    float s = 0.f;
    #pragma unroll
    for (int i = 0; i < 12; i++) {
        int c = lane + i * 32;
        float t = x[base + c];
        if (pos) t += pos[base + c];
        v[i] = t;
        s += t;
        if (hout) hout[base + c] = t;
    }
    #pragma unroll
    for (int o = 16; o; o >>= 1) s += __shfl_xor_sync(0xffffffffu, s, o);
    float mean = s * (1.0f / KC);
    float s2 = 0.f;
    #pragma unroll
    for (int i = 0; i < 12; i++) {
        float d = v[i] - mean;
        s2 += d * d;
    }
    #pragma unroll
    for (int o = 16; o; o >>= 1) s2 += __shfl_xor_sync(0xffffffffu, s2, o);
    float inv = rsqrtf(s2 * (1.0f / KC) + 1e-5f);
    size_t obase = outmap ? (size_t)outmap[row] * KC : base;
    #pragma unroll
    for (int i = 0; i < 12; i++) {
        int c = lane + i * 32;
        hn[obase + c] = (v[i] - mean) * inv * w[c] + bb[c];
    }
}

// ---------------- tensor-core masked flash attention ------------------------
// R9 structure (128 threads, 64 q/CTA, warp group-liveness skipping) with
// DOUBLE-BUFFERED K/V staging: cp.async for tile t+1 overlaps tile t compute.
// Dynamic smem: 2 stages x (64x68 + 64x72) floats = 71,680 B.
// P aliases the CURRENT stage's ks (staging writes the other stage).
#define AT_KS 68
#define AT_VS 72
#define AT_PS 68
#define AT_ST (64*AT_KS + 64*AT_VS)   // 8960 floats per stage
__global__ __launch_bounds__(128)
void attn_mma_kernel(const float* __restrict__ qkv,
                     const unsigned long long* __restrict__ nbrmask,
                     float* __restrict__ o) {
    extern __shared__ float asmem[];
    const int qt = blockIdx.x, h = blockIdx.y, b = blockIdx.z;
    const int tid  = threadIdx.x;
    const int lane = tid & 31;
    const int w    = tid >> 5;
    const int g    = lane >> 2;
    const int c    = lane & 3;

    const int qr_a = qt * 64 + w * 16 + g;
    const int qr_b = qr_a + 8;
    const int qa = min(qr_a, KV - 1);
    const int qb = min(qr_b, KV - 1);

    float qf[8][4];
    {
        const float* Qa = qkv + ((size_t)b * KV + qa) * (3*KC) + h * KDH;
        const float* Qb = qkv + ((size_t)b * KV + qb) * (3*KC) + h * KDH;
        #pragma unroll
        for (int k8 = 0; k8 < 8; k8++) {
            qf[k8][0] = tf32r(Qa[k8*8 + c])     * 0.125f;
            qf[k8][1] = tf32r(Qb[k8*8 + c])     * 0.125f;
            qf[k8][2] = tf32r(Qa[k8*8 + c + 4]) * 0.125f;
            qf[k8][3] = tf32r(Qb[k8*8 + c + 4]) * 0.125f;
        }
    }
    const unsigned long long* mra = nbrmask + ((size_t)b*KV + qa) * KTILES;
    const unsigned long long* mrb = nbrmask + ((size_t)b*KV + qb) * KTILES;

    float m0 = -1e30f, m1 = -1e30f, l0 = 0.f, l1 = 0.f;
    float oacc[8][4];
    #pragma unroll
    for (int nt = 0; nt < 8; nt++)
        #pragma unroll
        for (int r = 0; r < 4; r++) oacc[nt][r] = 0.f;

    // attention tile staging into stage buffer (ktArg & 1)
    #define ASTAGE(ktArg)                                                  \
    do {                                                                   \
        const int cnt_ = min(64, KV - (ktArg) * 64);                       \
        float* ks_ = asmem + ((ktArg) & 1) * AT_ST;                        \
        float* vs_ = ks_ + 64 * AT_KS;                                     \
        _Pragma("unroll")                                                  \
        for (int it = 0; it < 8; it++) {                                   \
            int idx = tid + it * 128;                                      \
            int j = idx >> 4, d4 = idx & 15;                               \
            int jc = min(j, cnt_ - 1);                                     \
            const float* src = qkv + ((size_t)b * KV + (ktArg)*64 + jc)    \
                             * (3*KC) + h * KDH + d4 * 4;                  \
            unsigned sz = (j < cnt_) ? 16u : 0u;                           \
            CP16Z(smem_u32(&ks_[j * AT_KS + d4 * 4]), src + KC,   sz);     \
            CP16Z(smem_u32(&vs_[j * AT_VS + d4 * 4]), src + 2*KC, sz);     \
        }                                                                  \
        asm volatile("cp.async.commit_group;\n");                          \
    } while (0)

    ASTAGE(0);

    for (int kt = 0; kt < KTILES; kt++) {
        // prefetch next tile into the other stage, then wait for current
        if (kt + 1 < KTILES) {
            ASTAGE(kt + 1);
            asm volatile("cp.async.wait_group 1;\n");
        } else {
            asm volatile("cp.async.wait_group 0;\n");
        }
        __syncthreads();

        float* ks = asmem + (kt & 1) * AT_ST;
        float* vs = ks + 64 * AT_KS;
        float* spw = &ks[w * 16 * AT_PS];   // P aliases current ks

        const unsigned long long mwa = mra[kt];
        const unsigned long long mwb = mrb[kt];
        // warp-union mask -> 8-bit key-group liveness (warp-uniform)
        unsigned long long mwu = mwa | mwb;
        #pragma unroll
        for (int off = 1; off < 32; off <<= 1)
            mwu |= __shfl_xor_sync(0xffffffffu, mwu, off);
        unsigned lv = 0;
        #pragma unroll
        for (int kg = 0; kg < 8; kg++)
            if ((mwu >> (kg * 8)) & 0xFFull) lv |= 1u << kg;

        float sacc[8][4];
        if (lv) {
            #pragma unroll
            for (int nt = 0; nt < 8; nt++)
                #pragma unroll
                for (int r = 0; r < 4; r++) sacc[nt][r] = 0.f;
            #pragma unroll
            for (int k8 = 0; k8 < 8; k8++) {
                #pragma unroll
                for (int nt = 0; nt < 8; nt++) {
                    if (!((lv >> nt) & 1)) continue;
                    unsigned bf[2];
                    const float* pb = &ks[(nt*8 + g) * AT_KS + k8*8 + c];
                    bf[0] = __float_as_uint(pb[0]);
                    bf[1] = __float_as_uint(pb[4]);
                    mma_tf32(sacc[nt], reinterpret_cast<const unsigned*>(qf[k8]), bf);
                }
            }
        }
        __syncthreads();   // ks reads done -> safe to alias-write P

        if (lv) {
            float tm0 = -1e30f, tm1 = -1e30f;
            #pragma unroll
            for (int nt = 0; nt < 8; nt++) {
                if (!((lv >> nt) & 1)) continue;
                int col = nt*8 + 2*c;
                sacc[nt][0] = ((mwa >> col)     & 1) ? sacc[nt][0] : -1e30f;
                sacc[nt][1] = ((mwa >> (col+1)) & 1) ? sacc[nt][1] : -1e30f;
                sacc[nt][2] = ((mwb >> col)     & 1) ? sacc[nt][2] : -1e30f;
                sacc[nt][3] = ((mwb >> (col+1)) & 1) ? sacc[nt][3] : -1e30f;
                tm0 = fmaxf(tm0, fmaxf(sacc[nt][0], sacc[nt][1]));
                tm1 = fmaxf(tm1, fmaxf(sacc[nt][2], sacc[nt][3]));
            }
            tm0 = fmaxf(tm0, __shfl_xor_sync(0xffffffffu, tm0, 1));
            tm0 = fmaxf(tm0, __shfl_xor_sync(0xffffffffu, tm0, 2));
            tm1 = fmaxf(tm1, __shfl_xor_sync(0xffffffffu, tm1, 1));
            tm1 = fmaxf(tm1, __shfl_xor_sync(0xffffffffu, tm1, 2));
            const float mn0 = fmaxf(m0, tm0);
            const float mn1 = fmaxf(m1, tm1);
            const float cr0 = __expf(m0 - mn0);
            const float cr1 = __expf(m1 - mn1);
            m0 = mn0; m1 = mn1;

            float ps0 = 0.f, ps1 = 0.f;
            #pragma unroll
            for (int nt = 0; nt < 8; nt++) {
                if (!((lv >> nt) & 1)) continue;
                int col = nt*8 + 2*c;
                float p00 = (sacc[nt][0] > -1e29f) ? __expf(sacc[nt][0] - mn0) : 0.f;
                float p01 = (sacc[nt][1] > -1e29f) ? __expf(sacc[nt][1] - mn0) : 0.f;
                float p10 = (sacc[nt][2] > -1e29f) ? __expf(sacc[nt][2] - mn1) : 0.f;
                float p11 = (sacc[nt][3] > -1e29f) ? __expf(sacc[nt][3] - mn1) : 0.f;
                ps0 += p00 + p01;
                ps1 += p10 + p11;
                *reinterpret_cast<float2*>(&spw[g * AT_PS + col]) =
                    make_float2(tf32r(p00), tf32r(p01));
                *reinterpret_cast<float2*>(&spw[(g + 8) * AT_PS + col]) =
                    make_float2(tf32r(p10), tf32r(p11));
            }
            ps0 += __shfl_xor_sync(0xffffffffu, ps0, 1);
            ps0 += __shfl_xor_sync(0xffffffffu, ps0, 2);
            ps1 += __shfl_xor_sync(0xffffffffu, ps1, 1);
            ps1 += __shfl_xor_sync(0xffffffffu, ps1, 2);
            l0 = l0 * cr0 + ps0;
            l1 = l1 * cr1 + ps1;
            #pragma unroll
            for (int nt = 0; nt < 8; nt++) {
                oacc[nt][0] *= cr0; oacc[nt][1] *= cr0;
                oacc[nt][2] *= cr1; oacc[nt][3] *= cr1;
            }
            __syncwarp();

            // O += P @ V (skip dead key-groups k8)
            #pragma unroll
            for (int k8 = 0; k8 < 8; k8++) {
                if (!((lv >> k8) & 1)) continue;
                unsigned af[4];
                af[0] = __float_as_uint(spw[g * AT_PS + k8*8 + c]);
                af[1] = __float_as_uint(spw[(g + 8) * AT_PS + k8*8 + c]);
                af[2] = __float_as_uint(spw[g * AT_PS + k8*8 + c + 4]);
                af[3] = __float_as_uint(spw[(g + 8) * AT_PS + k8*8 + c + 4]);
                #pragma unroll
                for (int nt = 0; nt < 8; nt++) {
                    unsigned bf[2];
                    bf[0] = __float_as_uint(vs[(k8*8 + c)     * AT_VS + nt*8 + g]);
                    bf[1] = __float_as_uint(vs[(k8*8 + c + 4) * AT_VS + nt*8 + g]);
                    mma_tf32(oacc[nt], af, bf);
                }
            }
        }
        __syncthreads();   // all reads of this stage done before re-staging
    }

    const float il0 = 1.0f / l0;   // self always unmasked -> l > 0
    const float il1 = 1.0f / l1;
    if (qr_a < KV) {
        size_t ob = ((size_t)b * KV + qr_a) * KC + h * KDH;
        #pragma unroll
        for (int nt = 0; nt < 8; nt++)
            *reinterpret_cast<float2*>(&o[ob + nt*8 + 2*c]) =
                make_float2(oacc[nt][0] * il0, oacc[nt][1] * il0);
    }
    if (qr_b < KV) {
        size_t ob = ((size_t)b * KV + qr_b) * KC + h * KDH;
        #pragma unroll
        for (int nt = 0; nt < 8; nt++)
            *reinterpret_cast<float2*>(&o[ob + nt*8 + 2*c]) =
                make_float2(oacc[nt][2] * il1, oacc[nt][3] * il1);
    }
}

// ---------------- launcher ----------------
extern "C" void kernel_launch(void* const* d_in, const int* in_sizes, int n_in,
                              void* d_out, int out_size) {
    const float* tokens  = (const float*)d_in[0];
    const float* centers = (const float*)d_in[1];
    const void*  mask    = d_in[2];
    const float* pos_w1  = (const float*)d_in[3];
    const float* pos_b1  = (const float*)d_in[4];
    const float* pos_w2  = (const float*)d_in[5];
    const float* pos_b2  = (const float*)d_in[6];
    const float* ln1_w   = (const float*)d_in[7];
    const float* ln1_b   = (const float*)d_in[8];
    const float* qkv_w   = (const float*)d_in[9];
    const float* qkv_b   = (const float*)d_in[10];
    const float* proj_w  = (const float*)d_in[11];
    const float* proj_b  = (const float*)d_in[12];
    const float* ln2_w   = (const float*)d_in[13];
    const float* ln2_b   = (const float*)d_in[14];
    const float* fc1_w   = (const float*)d_in[15];
    const float* fc1_b   = (const float*)d_in[16];
    const float* fc2_w   = (const float*)d_in[17];
    const float* fc2_b   = (const float*)d_in[18];
    const float* lnf_w   = (const float*)d_in[19];
    const float* lnf_b   = (const float*)d_in[20];

    float *bufA, *bufB, *pos, *hn, *qkv, *obuf, *t4, *ctr;
    int *order, *sidx, *outrow;
    unsigned long long* nbrmask;
    cudaGetSymbolAddress((void**)&bufA,   g_bufA);
    cudaGetSymbolAddress((void**)&bufB,   g_bufB);
    cudaGetSymbolAddress((void**)&pos,    g_pos);
    cudaGetSymbolAddress((void**)&hn,     g_hn);
    cudaGetSymbolAddress((void**)&qkv,    g_qkv);
    cudaGetSymbolAddress((void**)&obuf,   g_obuf);
    cudaGetSymbolAddress((void**)&t4,     g_t4);
    cudaGetSymbolAddress((void**)&ctr,    g_ctr);
    cudaGetSymbolAddress((void**)&order,  g_order);
    cudaGetSymbolAddress((void**)&sidx,   g_sidx);
    cudaGetSymbolAddress((void**)&outrow, g_outrow);
    cudaGetSymbolAddress((void**)&nbrmask, g_nbrmask);

    const int GEMM_SMEM = 2 * GST * sizeof(float);    // 71,680 B
    const int ATT_SMEM  = 2 * AT_ST * sizeof(float);  // 71,680 B
    cudaFuncSetAttribute(gemm_tf32_kernel,
                         cudaFuncAttributeMaxDynamicSharedMemorySize, GEMM_SMEM);
    cudaFuncSetAttribute(attn_mma_kernel,
                         cudaFuncAttributeMaxDynamicSharedMemorySize, ATT_SMEM);

    const int M = KBV;                 // 13120
    const dim3 blk(256);
    const int gyT = (M + 127) / 128;
    const int gyF = (M + 63) / 64;
    const int lnG = M / 8;             // 1640

    // ragged pack + spatial sort
    build_order_kernel<<<KB, 32>>>(mask, order);
    sort_kernel<<<KB, 256>>>(centers, order, sidx, outrow);
    gather_kernel<<<KBV, KC>>>(tokens, centers, order, sidx, bufA, ctr);

    // neighbor bitmask (sorted order; reused by all 36 attention passes)
    mask_kernel<<<dim3((KV + 127) / 128, KB), 128>>>(ctr, nbrmask);

    // positional MLP
    gemm_kernel<<<dim3(KC/64, gyF), blk>>>(ctr, pos_w1, pos_b1, hn, M, 3, KC, 1, 0);
    gemm_tf32_kernel<<<dim3(KC/128, gyT), blk, GEMM_SMEM>>>(hn, pos_w2, pos_b2, pos,
                                                            M, KC, KC, 0, 0);

    float* cur = bufA;
    float* oth = bufB;
    for (int l = 0; l < KDEPTH; l++) {
        ln_kernel<<<lnG, 256>>>(cur, pos, oth, hn, ln1_w + l*KC, ln1_b + l*KC, nullptr);
        gemm_tf32_kernel<<<dim3(3*KC/128, gyT), blk, GEMM_SMEM>>>(
            hn, qkv_w + (size_t)l*KC*3*KC, qkv_b + (size_t)l*3*KC, qkv,
            M, KC, 3*KC, 0, 0);
        attn_mma_kernel<<<dim3(KTILES, KH, KB), 128, ATT_SMEM>>>(qkv, nbrmask, obuf);
        gemm_tf32_kernel<<<dim3(KC/128, gyT), blk, GEMM_SMEM>>>(
            obuf, proj_w + (size_t)l*KC*KC, proj_b + (size_t)l*KC, oth,
            M, KC, KC, 0, 1);
        ln_kernel<<<lnG, 256>>>(oth, nullptr, nullptr, hn, ln2_w + l*KC, ln2_b + l*KC, nullptr);
        gemm_tf32_kernel<<<dim3(4*KC/128, gyT), blk, GEMM_SMEM>>>(
            hn, fc1_w + (size_t)l*KC*4*KC, fc1_b + (size_t)l*4*KC, t4,
            M, KC, 4*KC, 1, 0);
        gemm_tf32_kernel<<<dim3(KC/128, gyT), blk, GEMM_SMEM>>>(
            t4, fc2_w + (size_t)l*4*KC*KC, fc2_b + (size_t)l*KC, oth,
            M, 4*KC, KC, 0, 1);
        float* tmp = cur; cur = oth; oth = tmp;
    }
    // final LN, scattered back to original visible order
    ln_kernel<<<lnG, 256>>>(cur, nullptr, nullptr, (float*)d_out, lnf_w, lnf_b, outrow);
}

// round 12
// speedup vs baseline: 1.0836x; 1.0477x over previous
#include <cuda_runtime.h>
#include <math.h>
#include <stdint.h>

// ---------------- problem constants ----------------
#define KB   16          // batch
#define KG   2048        // group count
#define KC   384         // channels
#define KH   6           // heads
#define KDH  64          // head dim
#define KV   820         // visible tokens per row
#define KDEPTH 6
#define KBV  (KB*KV)     // 13120 rows
#define KR2  0.16f       // radius^2
#define KTILES 13        // ceil(KV/64)

// ---------------- static device scratch (no allocs allowed) ----------------
__device__ float g_bufA[KBV*KC];
__device__ float g_bufB[KBV*KC];
__device__ float g_pos [KBV*KC];
__device__ float g_hn  [KBV*KC];
__device__ float g_qkv [KBV*3*KC];
__device__ float g_obuf[KBV*KC];
__device__ float g_t4  [KBV*4*KC];
__device__ float g_ctr [KBV*3];
__device__ int   g_order[KBV];
__device__ int   g_sidx [KBV];
__device__ int   g_outrow[KBV];
__device__ unsigned long long g_nbrmask[KBV*KTILES];

// ---------------- helpers ----------------
__device__ __forceinline__ float gelu_tanh(float x) {
    const float c = 0.7978845608028654f;
    float inner = c * (x + 0.044715f * x * x * x);
    return 0.5f * x * (1.0f + tanhf(inner));
}

__device__ __forceinline__ float tf32r(float x) {
    unsigned u;
    asm("cvt.rna.tf32.f32 %0, %1;" : "=r"(u) : "f"(x));
    return __uint_as_float(u);
}

// bare MUFU.EX2 (independent of -use_fast_math)
__device__ __forceinline__ float ex2(float x) {
    float r;
    asm("ex2.approx.f32 %0, %1;" : "=f"(r) : "f"(x));
    return r;
}

__device__ __forceinline__ void mma_tf32(float* d, const unsigned* a,
                                         const unsigned* b) {
    asm volatile(
        "mma.sync.aligned.m16n8k8.row.col.f32.tf32.tf32.f32 "
        "{%0,%1,%2,%3}, {%4,%5,%6,%7}, {%8,%9}, {%0,%1,%2,%3};\n"
        : "+f"(d[0]), "+f"(d[1]), "+f"(d[2]), "+f"(d[3])
        : "r"(a[0]), "r"(a[1]), "r"(a[2]), "r"(a[3]),
          "r"(b[0]), "r"(b[1]));
}

__device__ __forceinline__ unsigned smem_u32(const void* p) {
    unsigned r;
    asm("{ .reg .u64 t; cvta.to.shared.u64 t, %1; cvt.u32.u64 %0, t; }"
        : "=r"(r) : "l"(p));
    return r;
}

#define CP16(dst, src) \
    asm volatile("cp.async.cg.shared.global [%0], [%1], 16;\n" \
                 :: "r"(dst), "l"(src))
#define CP16Z(dst, src, sz) \
    asm volatile("cp.async.cg.shared.global [%0], [%1], 16, %2;\n" \
                 :: "r"(dst), "l"(src), "r"(sz))

__device__ __forceinline__ unsigned part1by2(unsigned x) {
    x &= 0x3ff;
    x = (x | (x << 16)) & 0x030000FFu;
    x = (x | (x << 8))  & 0x0300F00Fu;
    x = (x | (x << 4))  & 0x030C30C3u;
    x = (x | (x << 2))  & 0x09249249u;
    return x;
}

// ---------------- ragged pack ----------------
__global__ void build_order_kernel(const void* mask, int* order) {
    int b = blockIdx.x;
    if (threadIdx.x != 0) return;
    const unsigned char* m8 = (const unsigned char*)mask;
    int zc = 0;
    for (int i = 0; i < KG; i++) zc += (m8[(size_t)b*KG + i] == 0);
    int cnt = 0;
    if (zc == KV) {
        for (int i = 0; i < KG && cnt < KV; i++)
            if (m8[(size_t)b*KG + i] == 0) order[b*KV + cnt++] = i;
    } else {
        const int* m32 = (const int*)mask;
        for (int i = 0; i < KG && cnt < KV; i++)
            if (m32[(size_t)b*KG + i] == 0) order[b*KV + cnt++] = i;
    }
}

// ---------------- Morton sort of visible tokens (per batch, bitonic) --------
__global__ void sort_kernel(const float* __restrict__ centers,
                            const int* __restrict__ order,
                            int* __restrict__ sidx, int* __restrict__ outrow) {
    const int b = blockIdx.x;
    __shared__ unsigned keys[1024];
    __shared__ int      vals[1024];
    const int tid = threadIdx.x;  // 256
    for (int i = tid; i < 1024; i += 256) {
        if (i < KV) {
            int tok = order[b*KV + i];
            size_t cb = ((size_t)b*KG + tok) * 3;
            float x = centers[cb + 0], y = centers[cb + 1], z = centers[cb + 2];
            unsigned ux = min(1023, max(0, (int)(x * 1024.f)));
            unsigned uy = min(1023, max(0, (int)(y * 1024.f)));
            unsigned uz = min(1023, max(0, (int)(z * 1024.f)));
            keys[i] = (part1by2(uz) << 2) | (part1by2(uy) << 1) | part1by2(ux);
            vals[i] = i;
        } else {
            keys[i] = 0xFFFFFFFFu;
            vals[i] = i;
        }
    }
    __syncthreads();
    for (int k = 2; k <= 1024; k <<= 1) {
        for (int j = k >> 1; j > 0; j >>= 1) {
            for (int i = tid; i < 1024; i += 256) {
                int ixj = i ^ j;
                if (ixj > i) {
                    bool up = ((i & k) == 0);
                    unsigned ka = keys[i], kb2 = keys[ixj];
                    if ((ka > kb2) == up) {
                        keys[i] = kb2; keys[ixj] = ka;
                        int t = vals[i]; vals[i] = vals[ixj]; vals[ixj] = t;
                    }
                }
            }
            __syncthreads();
        }
    }
    for (int i = tid; i < KV; i += 256) {
        sidx[b*KV + i]   = vals[i];
        outrow[b*KV + i] = b*KV + vals[i];
    }
}

__global__ void gather_kernel(const float* __restrict__ tokens,
                              const float* __restrict__ centers,
                              const int* __restrict__ order,
                              const int* __restrict__ sidx,
                              float* __restrict__ x, float* __restrict__ ctr) {
    int bv = blockIdx.x;
    int b = bv / KV;
    int src = order[b*KV + sidx[bv]];
    int tid = threadIdx.x;  // 384
    x[(size_t)bv*KC + tid] = tokens[((size_t)b*KG + src)*KC + tid];
    if (tid < 3) ctr[(size_t)bv*3 + tid] = centers[((size_t)b*KG + src)*3 + tid];
}

// ---------------- neighbor bitmask precompute (sorted order) ----------------
__global__ void mask_kernel(const float* __restrict__ ctr,
                            unsigned long long* __restrict__ nbrmask) {
    const int b = blockIdx.y;
    const int q = blockIdx.x * 128 + threadIdx.x;
    __shared__ float sc[KV][3];
    for (int i = threadIdx.x; i < KV; i += 128) {
        size_t cb = ((size_t)b*KV + i) * 3;
        sc[i][0] = ctr[cb + 0];
        sc[i][1] = ctr[cb + 1];
        sc[i][2] = ctr[cb + 2];
    }
    __syncthreads();
    if (q >= KV) return;
    const float qc0 = sc[q][0], qc1 = sc[q][1], qc2 = sc[q][2];
    unsigned long long* out = nbrmask + (size_t)(b*KV + q) * KTILES;
    for (int kt = 0; kt < KTILES; kt++) {
        unsigned long long w = 0;
        const int base = kt * 64;
        const int cnt = min(64, KV - base);
        for (int j = 0; j < cnt; j++) {
            float dx = qc0 - sc[base + j][0];
            float dy = qc1 - sc[base + j][1];
            float dz = qc2 - sc[base + j][2];
            float d2 = fmaf(dx, dx, fmaf(dy, dy, dz * dz));
            if (d2 < KR2) w |= 1ull << j;
        }
        out[kt] = w;
    }
}

// ---------------- FFMA GEMM (tiny-K pos MLP layer 1) ----------------
__global__ void gemm_kernel(const float* __restrict__ A, const float* __restrict__ W,
                            const float* __restrict__ bias, float* __restrict__ C,
                            int M, int K, int N, int act, int addC) {
    __shared__ float As[16][65];
    __shared__ float Bs[16][65];
    const int tid = threadIdx.x;
    const int tx = tid & 15;
    const int ty = tid >> 4;
    const int bm = blockIdx.y * 64;
    const int bn = blockIdx.x * 64;
    float acc[4][4];
    #pragma unroll
    for (int i = 0; i < 4; i++)
        #pragma unroll
        for (int j = 0; j < 4; j++) acc[i][j] = 0.f;

    for (int k0 = 0; k0 < K; k0 += 16) {
        #pragma unroll
        for (int t = 0; t < 4; t++) {
            int idx = tid + t * 256;
            int m  = idx >> 4;
            int kk = idx & 15;
            int gm = bm + m, gk = k0 + kk;
            float v = 0.f;
            if (gk < K && gm < M) v = A[(size_t)gm * K + gk];
            As[kk][m] = v;
        }
        #pragma unroll
        for (int t = 0; t < 4; t++) {
            int idx = tid + t * 256;
            int kk = idx >> 6;
            int n  = idx & 63;
            int gk = k0 + kk, gn = bn + n;
            float v = 0.f;
            if (gk < K && gn < N) v = W[(size_t)gk * N + gn];
            Bs[kk][n] = v;
        }
        __syncthreads();
        #pragma unroll
        for (int kk = 0; kk < 16; kk++) {
            float a[4], b[4];
            #pragma unroll
            for (int i = 0; i < 4; i++) a[i] = As[kk][ty*4 + i];
            #pragma unroll
            for (int j = 0; j < 4; j++) b[j] = Bs[kk][tx*4 + j];
            #pragma unroll
            for (int i = 0; i < 4; i++)
                #pragma unroll
                for (int j = 0; j < 4; j++)
                    acc[i][j] = fmaf(a[i], b[j], acc[i][j]);
        }
        __syncthreads();
    }
    #pragma unroll
    for (int i = 0; i < 4; i++) {
        int gm = bm + ty*4 + i;
        if (gm >= M) continue;
        #pragma unroll
        for (int j = 0; j < 4; j++) {
            int gn = bn + tx*4 + j;
            if (gn >= N) continue;
            float v = acc[i][j] + bias[gn];
            if (act) v = gelu_tanh(v);
            size_t off = (size_t)gm * N + gn;
            if (addC) v += C[off];
            C[off] = v;
        }
    }
}

// ---------------- tf32 tensor-core GEMM (k-tile 32, cp.async 2-stage) -------
#define GA_S 36
#define GB_S 136
#define GST  (128*GA_S + 32*GB_S)   // 8960 floats per stage
__global__ __launch_bounds__(256, 2)
void gemm_tf32_kernel(const float* __restrict__ A, const float* __restrict__ W,
                      const float* __restrict__ bias, float* __restrict__ C,
                      int M, int K, int N, int act, int addC) {
    extern __shared__ float gsm[];

    const int tid  = threadIdx.x;
    const int lane = tid & 31;
    const int w    = tid >> 5;
    const int wm   = (w & 3) * 32;
    const int wn   = (w >> 2) * 64;
    const int bm   = blockIdx.y * 128;
    const int bn   = blockIdx.x * 128;
    const int g    = lane >> 2, c = lane & 3;

    float acc[2][8][4];
    #pragma unroll
    for (int mt = 0; mt < 2; mt++)
        #pragma unroll
        for (int nt = 0; nt < 8; nt++)
            #pragma unroll
            for (int r = 0; r < 4; r++) acc[mt][nt][r] = 0.f;

    const int ktiles = K >> 5;

    #define GSTAGE_TILE(ktArg)                                            \
    do {                                                                  \
        float* sA_ = gsm + ((ktArg) & 1) * GST;                           \
        float* sB_ = sA_ + 128 * GA_S;                                    \
        const int k0_ = (ktArg) << 5;                                     \
        _Pragma("unroll")                                                 \
        for (int t = 0; t < 4; t++) {                                     \
            int i = tid + t * 256;                                        \
            int row = i >> 3, kq = (i & 7) * 4;                           \
            int gm = bm + row; if (gm > M - 1) gm = M - 1;                \
            CP16(smem_u32(&sA_[row * GA_S + kq]),                         \
                 A + (size_t)gm * K + k0_ + kq);                          \
        }                                                                 \
        _Pragma("unroll")                                                 \
        for (int t = 0; t < 4; t++) {                                     \
            int i = tid + t * 256;                                        \
            int kr = i >> 5, nq = (i & 31) * 4;                           \
            CP16(smem_u32(&sB_[kr * GB_S + nq]),                          \
                 W + (size_t)(k0_ + kr) * N + bn + nq);                   \
        }                                                                 \
        asm volatile("cp.async.commit_group;\n");                         \
    } while (0)

    GSTAGE_TILE(0);

    for (int kt = 0; kt < ktiles; kt++) {
        if (kt + 1 < ktiles) {
            GSTAGE_TILE(kt + 1);
            asm volatile("cp.async.wait_group 1;\n");
        } else {
            asm volatile("cp.async.wait_group 0;\n");
        }
        __syncthreads();

        const float* sA = gsm + (kt & 1) * GST;
        const float* sB = sA + 128 * GA_S;
        #pragma unroll
        for (int k8 = 0; k8 < 4; k8++) {
            const int kb = k8 * 8;
            unsigned af[2][4], bf[8][2];
            const int arow = wm + g;
            #pragma unroll
            for (int mt = 0; mt < 2; mt++) {
                const float* pa = &sA[(arow + mt * 16) * GA_S + kb + c];
                af[mt][0] = __float_as_uint(pa[0]);
                af[mt][1] = __float_as_uint(pa[8 * GA_S]);
                af[mt][2] = __float_as_uint(pa[4]);
                af[mt][3] = __float_as_uint(pa[8 * GA_S + 4]);
            }
            #pragma unroll
            for (int nt = 0; nt < 8; nt++) {
                const float* pb = &sB[(kb + c) * GB_S + wn + nt * 8 + g];
                bf[nt][0] = __float_as_uint(pb[0]);
                bf[nt][1] = __float_as_uint(pb[4 * GB_S]);
            }
            #pragma unroll
            for (int mt = 0; mt < 2; mt++)
                #pragma unroll
                for (int nt = 0; nt < 8; nt++)
                    mma_tf32(acc[mt][nt], af[mt], bf[nt]);
        }
        __syncthreads();
    }

    #pragma unroll
    for (int mt = 0; mt < 2; mt++) {
        int rbase = bm + wm + mt * 16 + g;
        #pragma unroll
        for (int half = 0; half < 2; half++) {
            int r = rbase + half * 8;
            if (r >= M) continue;
            #pragma unroll
            for (int nt = 0; nt < 8; nt++) {
                int cix = bn + wn + nt * 8 + 2 * c;
                float v0 = acc[mt][nt][half * 2 + 0] + bias[cix];
                float v1 = acc[mt][nt][half * 2 + 1] + bias[cix + 1];
                if (act) { v0 = gelu_tanh(v0); v1 = gelu_tanh(v1); }
                size_t off = (size_t)r * N + cix;
                if (addC) { v0 += C[off]; v1 += C[off + 1]; }
                float2 vv = make_float2(v0, v1);
                *reinterpret_cast<float2*>(&C[off]) = vv;
            }
        }
    }
}

// ---------------- LayerNorm (warp per row; optional output remap) -----------
__global__ __launch_bounds__(256)
void ln_kernel(const float* __restrict__ x, const float* __restrict__ pos,
               float* __restrict__ hout, float* __restrict__ hn,
               const float* __restrict__ w, const float* __restrict__ bb,
               const int* __restrict__ outmap) {
    const int row  = blockIdx.x * 8 + (threadIdx.x >> 5);
    const int lane = threadIdx.x & 31;
    size_t base = (size_t)row * KC;
    float v[12];
    float s = 0.f;
    #pragma unroll
    for (int i = 0; i < 12; i++) {
        int c = lane + i * 32;
        float t = x[base + c];
        if (pos) t += pos[base + c];
        v[i] = t;
        s += t;
        if (hout) hout[base + c] = t;
    }
    #pragma unroll
    for (int o = 16; o; o >>= 1) s += __shfl_xor_sync(0xffffffffu, s, o);
    float mean = s * (1.0f / KC);
    float s2 = 0.f;
    #pragma unroll
    for (int i = 0; i < 12; i++) {
        float d = v[i] - mean;
        s2 += d * d;
    }
    #pragma unroll
    for (int o = 16; o; o >>= 1) s2 += __shfl_xor_sync(0xffffffffu, s2, o);
    float inv = rsqrtf(s2 * (1.0f / KC) + 1e-5f);
    size_t obase = outmap ? (size_t)outmap[row] * KC : base;
    #pragma unroll
    for (int i = 0; i < 12; i++) {
        int c = lane + i * 32;
        hn[obase + c] = (v[i] - mean) * inv * w[c] + bb[c];
    }
}

// ---------------- tensor-core masked flash attention ------------------------
// 128 threads, 64 q/CTA, warp-uniform 8-key-group liveness skipping.
// LOG2-DOMAIN softmax: q pre-scaled by 0.125*log2(e); p = ex2(s - m) with
// sentinel -3e38 for masked scores (m init -1e38) -> masked p underflows to
// exactly 0 without a select. P aliases ks after S-MMAs.
#define AT_KS 68
#define AT_VS 72
#define AT_PS 68
#define QSCALE 0.1803368801111204f   // 0.125 * log2(e)
#define SNEG  -3e38f
#define MINIT -1e38f
__global__ __launch_bounds__(128)
void attn_mma_kernel(const float* __restrict__ qkv,
                     const unsigned long long* __restrict__ nbrmask,
                     float* __restrict__ o) {
    __shared__ float ks[64 * AT_KS];          // aliased as P buffer
    __shared__ float vs[64 * AT_VS];
    const int qt = blockIdx.x, h = blockIdx.y, b = blockIdx.z;
    const int tid  = threadIdx.x;
    const int lane = tid & 31;
    const int w    = tid >> 5;
    const int g    = lane >> 2;
    const int c    = lane & 3;
    float* spw = &ks[w * 16 * AT_PS];

    const int qr_a = qt * 64 + w * 16 + g;
    const int qr_b = qr_a + 8;
    const int qa = min(qr_a, KV - 1);
    const int qb = min(qr_b, KV - 1);

    float qf[8][4];
    {
        const float* Qa = qkv + ((size_t)b * KV + qa) * (3*KC) + h * KDH;
        const float* Qb = qkv + ((size_t)b * KV + qb) * (3*KC) + h * KDH;
        #pragma unroll
        for (int k8 = 0; k8 < 8; k8++) {
            qf[k8][0] = Qa[k8*8 + c]     * QSCALE;
            qf[k8][1] = Qb[k8*8 + c]     * QSCALE;
            qf[k8][2] = Qa[k8*8 + c + 4] * QSCALE;
            qf[k8][3] = Qb[k8*8 + c + 4] * QSCALE;
        }
    }
    const unsigned long long* mra = nbrmask + ((size_t)b*KV + qa) * KTILES;
    const unsigned long long* mrb = nbrmask + ((size_t)b*KV + qb) * KTILES;

    float m0 = MINIT, m1 = MINIT, l0 = 0.f, l1 = 0.f;
    float oacc[8][4];
    #pragma unroll
    for (int nt = 0; nt < 8; nt++)
        #pragma unroll
        for (int r = 0; r < 4; r++) oacc[nt][r] = 0.f;

    for (int kt = 0; kt < KTILES; kt++) {
        const int cnt = min(64, KV - kt * 64);
        // stage K/V tile via cp.async (zero-fill beyond cnt)
        #pragma unroll
        for (int it = 0; it < 8; it++) {
            int idx = tid + it * 128;
            int j = idx >> 4, d4 = idx & 15;
            int jc = min(j, cnt - 1);
            const float* src = qkv + ((size_t)b * KV + kt*64 + jc) * (3*KC)
                             + h * KDH + d4 * 4;
            unsigned sz = (j < cnt) ? 16u : 0u;
            CP16Z(smem_u32(&ks[j * AT_KS + d4 * 4]), src + KC,   sz);
            CP16Z(smem_u32(&vs[j * AT_VS + d4 * 4]), src + 2*KC, sz);
        }
        asm volatile("cp.async.commit_group;\n");
        asm volatile("cp.async.wait_group 0;\n");
        __syncthreads();

        const unsigned long long mwa = mra[kt];
        const unsigned long long mwb = mrb[kt];
        // warp-union mask -> 8-bit key-group liveness (REDUX on halves)
        unsigned long long mwu = mwa | mwb;
        unsigned ulo = __reduce_or_sync(0xffffffffu, (unsigned)(mwu & 0xffffffffull));
        unsigned uhi = __reduce_or_sync(0xffffffffu, (unsigned)(mwu >> 32));
        unsigned long long mwuw = ((unsigned long long)uhi << 32) | ulo;
        unsigned lv = 0;
        #pragma unroll
        for (int kg = 0; kg < 8; kg++)
            if ((mwuw >> (kg * 8)) & 0xFFull) lv |= 1u << kg;

        float sacc[8][4];
        if (lv) {
            #pragma unroll
            for (int nt = 0; nt < 8; nt++)
                #pragma unroll
                for (int r = 0; r < 4; r++) sacc[nt][r] = 0.f;
            #pragma unroll
            for (int k8 = 0; k8 < 8; k8++) {
                #pragma unroll
                for (int nt = 0; nt < 8; nt++) {
                    if (!((lv >> nt) & 1)) continue;
                    unsigned bf[2];
                    const float* pb = &ks[(nt*8 + g) * AT_KS + k8*8 + c];
                    bf[0] = __float_as_uint(pb[0]);
                    bf[1] = __float_as_uint(pb[4]);
                    mma_tf32(sacc[nt], reinterpret_cast<const unsigned*>(qf[k8]), bf);
                }
            }
        }
        __syncthreads();   // ks free -> P buffer

        if (lv) {
            float tm0 = SNEG, tm1 = SNEG;
            #pragma unroll
            for (int nt = 0; nt < 8; nt++) {
                if (!((lv >> nt) & 1)) continue;
                int col = nt*8 + 2*c;
                sacc[nt][0] = ((mwa >> col)     & 1) ? sacc[nt][0] : SNEG;
                sacc[nt][1] = ((mwa >> (col+1)) & 1) ? sacc[nt][1] : SNEG;
                sacc[nt][2] = ((mwb >> col)     & 1) ? sacc[nt][2] : SNEG;
                sacc[nt][3] = ((mwb >> (col+1)) & 1) ? sacc[nt][3] : SNEG;
                tm0 = fmaxf(tm0, fmaxf(sacc[nt][0], sacc[nt][1]));
                tm1 = fmaxf(tm1, fmaxf(sacc[nt][2], sacc[nt][3]));
            }
            tm0 = fmaxf(tm0, __shfl_xor_sync(0xffffffffu, tm0, 1));
            tm0 = fmaxf(tm0, __shfl_xor_sync(0xffffffffu, tm0, 2));
            tm1 = fmaxf(tm1, __shfl_xor_sync(0xffffffffu, tm1, 1));
            tm1 = fmaxf(tm1, __shfl_xor_sync(0xffffffffu, tm1, 2));
            const float mn0 = fmaxf(m0, tm0);
            const float mn1 = fmaxf(m1, tm1);
            const float cr0 = ex2(m0 - mn0);   // ex2(0)=1; huge-neg -> 0
            const float cr1 = ex2(m1 - mn1);
            m0 = mn0; m1 = mn1;

            float ps0 = 0.f, ps1 = 0.f;
            #pragma unroll
            for (int nt = 0; nt < 8; nt++) {
                if (!((lv >> nt) & 1)) continue;
                int col = nt*8 + 2*c;
                // unconditional: masked score = -3e38 -> ex2 underflows to 0
                float p00 = ex2(sacc[nt][0] - mn0);
                float p01 = ex2(sacc[nt][1] - mn0);
                float p10 = ex2(sacc[nt][2] - mn1);
                float p11 = ex2(sacc[nt][3] - mn1);
                ps0 += p00 + p01;
                ps1 += p10 + p11;
                *reinterpret_cast<float2*>(&spw[g * AT_PS + col]) =
                    make_float2(p00, p01);
                *reinterpret_cast<float2*>(&spw[(g + 8) * AT_PS + col]) =
                    make_float2(p10, p11);
            }
            ps0 += __shfl_xor_sync(0xffffffffu, ps0, 1);
            ps0 += __shfl_xor_sync(0xffffffffu, ps0, 2);
            ps1 += __shfl_xor_sync(0xffffffffu, ps1, 1);
            ps1 += __shfl_xor_sync(0xffffffffu, ps1, 2);
            l0 = l0 * cr0 + ps0;
            l1 = l1 * cr1 + ps1;
            #pragma unroll
            for (int nt = 0; nt < 8; nt++) {
                oacc[nt][0] *= cr0; oacc[nt][1] *= cr0;
                oacc[nt][2] *= cr1; oacc[nt][3] *= cr1;
            }
            __syncwarp();

            // O += P @ V (skip dead key-groups k8)
            #pragma unroll
            for (int k8 = 0; k8 < 8; k8++) {
                if (!((lv >> k8) & 1)) continue;
                unsigned af[4];
                af[0] = __float_as_uint(spw[g * AT_PS + k8*8 + c]);
                af[1] = __float_as_uint(spw[(g + 8) * AT_PS + k8*8 + c]);
                af[2] = __float_as_uint(spw[g * AT_PS + k8*8 + c + 4]);
                af[3] = __float_as_uint(spw[(g + 8) * AT_PS + k8*8 + c + 4]);
                #pragma unroll
                for (int nt = 0; nt < 8; nt++) {
                    unsigned bf[2];
                    bf[0] = __float_as_uint(vs[(k8*8 + c)     * AT_VS + nt*8 + g]);
                    bf[1] = __float_as_uint(vs[(k8*8 + c + 4) * AT_VS + nt*8 + g]);
                    mma_tf32(oacc[nt], af, bf);
                }
            }
        }
        __syncthreads();
    }

    const float il0 = 1.0f / l0;   // self always unmasked -> l > 0
    const float il1 = 1.0f / l1;
    if (qr_a < KV) {
        size_t ob = ((size_t)b * KV + qr_a) * KC + h * KDH;
        #pragma unroll
        for (int nt = 0; nt < 8; nt++)
            *reinterpret_cast<float2*>(&o[ob + nt*8 + 2*c]) =
                make_float2(oacc[nt][0] * il0, oacc[nt][1] * il0);
    }
    if (qr_b < KV) {
        size_t ob = ((size_t)b * KV + qr_b) * KC + h * KDH;
        #pragma unroll
        for (int nt = 0; nt < 8; nt++)
            *reinterpret_cast<float2*>(&o[ob + nt*8 + 2*c]) =
                make_float2(oacc[nt][2] * il1, oacc[nt][3] * il1);
    }
}

// ---------------- launcher ----------------
extern "C" void kernel_launch(void* const* d_in, const int* in_sizes, int n_in,
                              void* d_out, int out_size) {
    const float* tokens  = (const float*)d_in[0];
    const float* centers = (const float*)d_in[1];
    const void*  mask    = d_in[2];
    const float* pos_w1  = (const float*)d_in[3];
    const float* pos_b1  = (const float*)d_in[4];
    const float* pos_w2  = (const float*)d_in[5];
    const float* pos_b2  = (const float*)d_in[6];
    const float* ln1_w   = (const float*)d_in[7];
    const float* ln1_b   = (const float*)d_in[8];
    const float* qkv_w   = (const float*)d_in[9];
    const float* qkv_b   = (const float*)d_in[10];
    const float* proj_w  = (const float*)d_in[11];
    const float* proj_b  = (const float*)d_in[12];
    const float* ln2_w   = (const float*)d_in[13];
    const float* ln2_b   = (const float*)d_in[14];
    const float* fc1_w   = (const float*)d_in[15];
    const float* fc1_b   = (const float*)d_in[16];
    const float* fc2_w   = (const float*)d_in[17];
    const float* fc2_b   = (const float*)d_in[18];
    const float* lnf_w   = (const float*)d_in[19];
    const float* lnf_b   = (const float*)d_in[20];

    float *bufA, *bufB, *pos, *hn, *qkv, *obuf, *t4, *ctr;
    int *order, *sidx, *outrow;
    unsigned long long* nbrmask;
    cudaGetSymbolAddress((void**)&bufA,   g_bufA);
    cudaGetSymbolAddress((void**)&bufB,   g_bufB);
    cudaGetSymbolAddress((void**)&pos,    g_pos);
    cudaGetSymbolAddress((void**)&hn,     g_hn);
    cudaGetSymbolAddress((void**)&qkv,    g_qkv);
    cudaGetSymbolAddress((void**)&obuf,   g_obuf);
    cudaGetSymbolAddress((void**)&t4,     g_t4);
    cudaGetSymbolAddress((void**)&ctr,    g_ctr);
    cudaGetSymbolAddress((void**)&order,  g_order);
    cudaGetSymbolAddress((void**)&sidx,   g_sidx);
    cudaGetSymbolAddress((void**)&outrow, g_outrow);
    cudaGetSymbolAddress((void**)&nbrmask, g_nbrmask);

    const int GEMM_SMEM = 2 * GST * sizeof(float);   // 71,680 B
    cudaFuncSetAttribute(gemm_tf32_kernel,
                         cudaFuncAttributeMaxDynamicSharedMemorySize, GEMM_SMEM);

    const int M = KBV;                 // 13120
    const dim3 blk(256);
    const int gyT = (M + 127) / 128;
    const int gyF = (M + 63) / 64;
    const int lnG = M / 8;             // 1640

    // ragged pack + spatial sort
    build_order_kernel<<<KB, 32>>>(mask, order);
    sort_kernel<<<KB, 256>>>(centers, order, sidx, outrow);
    gather_kernel<<<KBV, KC>>>(tokens, centers, order, sidx, bufA, ctr);

    // neighbor bitmask (sorted order; reused by all 36 attention passes)
    mask_kernel<<<dim3((KV + 127) / 128, KB), 128>>>(ctr, nbrmask);

    // positional MLP
    gemm_kernel<<<dim3(KC/64, gyF), blk>>>(ctr, pos_w1, pos_b1, hn, M, 3, KC, 1, 0);
    gemm_tf32_kernel<<<dim3(KC/128, gyT), blk, GEMM_SMEM>>>(hn, pos_w2, pos_b2, pos,
                                                            M, KC, KC, 0, 0);

    float* cur = bufA;
    float* oth = bufB;
    for (int l = 0; l < KDEPTH; l++) {
        ln_kernel<<<lnG, 256>>>(cur, pos, oth, hn, ln1_w + l*KC, ln1_b + l*KC, nullptr);
        gemm_tf32_kernel<<<dim3(3*KC/128, gyT), blk, GEMM_SMEM>>>(
            hn, qkv_w + (size_t)l*KC*3*KC, qkv_b + (size_t)l*3*KC, qkv,
            M, KC, 3*KC, 0, 0);
        attn_mma_kernel<<<dim3(KTILES, KH, KB), 128>>>(qkv, nbrmask, obuf);
        gemm_tf32_kernel<<<dim3(KC/128, gyT), blk, GEMM_SMEM>>>(
            obuf, proj_w + (size_t)l*KC*KC, proj_b + (size_t)l*KC, oth,
            M, KC, KC, 0, 1);
        ln_kernel<<<lnG, 256>>>(oth, nullptr, nullptr, hn, ln2_w + l*KC, ln2_b + l*KC, nullptr);
        gemm_tf32_kernel<<<dim3(4*KC/128, gyT), blk, GEMM_SMEM>>>(
            hn, fc1_w + (size_t)l*KC*4*KC, fc1_b + (size_t)l*4*KC, t4,
            M, KC, 4*KC, 1, 0);
        gemm_tf32_kernel<<<dim3(KC/128, gyT), blk, GEMM_SMEM>>>(
            t4, fc2_w + (size_t)l*4*KC*KC, fc2_b + (size_t)l*KC, oth,
            M, 4*KC, KC, 0, 1);
        float* tmp = cur; cur = oth; oth = tmp;
    }
    // final LN, scattered back to original visible order
    ln_kernel<<<lnG, 256>>>(cur, nullptr, nullptr, (float*)d_out, lnf_w, lnf_b, outrow);
}